// round 1
// baseline (speedup 1.0000x reference)
#include <cuda_runtime.h>
#include <cstdint>

#define N_NODES 50000
#define N_EDGES 800000
#define IN_DIM  256
#define OUT_DIM 64
#define NEG_SLOPE 0.01f
#define TILE_M 128

typedef unsigned long long ull;

// ---------------- device scratch (no allocations allowed) ----------------
__device__ float g_z[N_NODES * OUT_DIM];     // 12.8 MB, L2-resident during node phase
__device__ float g_sl[N_NODES];
__device__ float g_sr[N_NODES];
__device__ int   g_off[N_NODES + 1];         // CSR offsets (by dst)
__device__ int   g_cur[N_NODES];             // scatter cursors
__device__ int   g_ssrc[N_EDGES];            // src ids sorted by dst
__device__ float g_se[N_EDGES];              // leaky(e) sorted by dst

// ---------------- GEMM: z = h @ W, f32x2-packed row pairs ----------------
// block = 256 threads, TILE_M=128 rows. Shared: W (64KB) + h paired (128KB).
__global__ void gemm_kernel(const float* __restrict__ h,
                            const float* __restrict__ W) {
    extern __shared__ float smem[];
    float*  Wsh = smem;                                 // [256][64]
    float2* hp  = (float2*)(smem + IN_DIM * OUT_DIM);   // [64 pairs][256 k]

    const int t    = threadIdx.x;
    const int row0 = blockIdx.x * TILE_M;

    // load W (coalesced, 64KB)
    #pragma unroll 4
    for (int i = t; i < IN_DIM * OUT_DIM; i += 256) Wsh[i] = W[i];

    // load h tile into row-paired layout: hp[p][k] = (h[2p][k], h[2p+1][k])
    for (int i = t; i < TILE_M * (IN_DIM / 4); i += 256) {
        int r  = i / (IN_DIM / 4);
        int k4 = i % (IN_DIM / 4);
        int gr = row0 + r;
        float4 v = (gr < N_NODES) ? ((const float4*)h)[gr * (IN_DIM / 4) + k4]
                                  : make_float4(0.f, 0.f, 0.f, 0.f);
        int p = r >> 1, half = r & 1;
        float* dst = (float*)&hp[p * IN_DIM + k4 * 4];
        dst[0 * 2 + half] = v.x;
        dst[1 * 2 + half] = v.y;
        dst[2 * 2 + half] = v.z;
        dst[3 * 2 + half] = v.w;
    }
    __syncthreads();

    const int c  = t & 63;          // output column
    const int g0 = (t >> 6) * 16;   // base row-pair (4 groups x 16 pairs)

    ull acc[16];
    #pragma unroll
    for (int g = 0; g < 16; g++) acc[g] = 0ULL;   // (0.f,0.f)

    #pragma unroll 2
    for (int k0 = 0; k0 < IN_DIM; k0 += 2) {
        float w0 = Wsh[k0 * OUT_DIM + c];
        float w1 = Wsh[(k0 + 1) * OUT_DIM + c];
        ull b0, b1;
        asm("mov.b64 %0, {%1, %1};" : "=l"(b0) : "r"(__float_as_uint(w0)));
        asm("mov.b64 %0, {%1, %1};" : "=l"(b1) : "r"(__float_as_uint(w1)));
        #pragma unroll
        for (int g = 0; g < 16; g++) {
            // 16B load: pairs for k0 and k0+1 (broadcast across the warp)
            ulonglong2 vv = *(const ulonglong2*)&hp[(g0 + g) * IN_DIM + k0];
            asm("fma.rn.f32x2 %0, %1, %2, %0;" : "+l"(acc[g]) : "l"(vv.x), "l"(b0));
            asm("fma.rn.f32x2 %0, %1, %2, %0;" : "+l"(acc[g]) : "l"(vv.y), "l"(b1));
        }
    }

    #pragma unroll
    for (int g = 0; g < 16; g++) {
        int p  = g0 + g;
        int r0 = row0 + 2 * p;
        float2 a = *(float2*)&acc[g];
        if (r0 < N_NODES)     g_z[r0 * OUT_DIM + c]       = a.x;
        if (r0 + 1 < N_NODES) g_z[(r0 + 1) * OUT_DIM + c] = a.y;
    }
}

// ---------------- s_l / s_r: per-node dot of z row with a_l / a_r ----------------
__global__ void s_kernel(const float* __restrict__ a_attn) {
    int gw   = (blockIdx.x * blockDim.x + threadIdx.x) >> 5;
    int lane = threadIdx.x & 31;
    if (gw >= N_NODES) return;
    float2 zv = *(const float2*)&g_z[gw * OUT_DIM + 2 * lane];
    float al0 = a_attn[2 * lane],      al1 = a_attn[2 * lane + 1];
    float ar0 = a_attn[64 + 2 * lane], ar1 = a_attn[64 + 2 * lane + 1];
    float sl = zv.x * al0 + zv.y * al1;
    float sr = zv.x * ar0 + zv.y * ar1;
    #pragma unroll
    for (int o = 16; o; o >>= 1) {
        sl += __shfl_xor_sync(0xffffffffu, sl, o);
        sr += __shfl_xor_sync(0xffffffffu, sr, o);
    }
    if (lane == 0) { g_sl[gw] = sl; g_sr[gw] = sr; }
}

// ---------------- CSR build ----------------
__global__ void zero_kernel() {
    int i = blockIdx.x * blockDim.x + threadIdx.x;
    if (i <= N_NODES) g_off[i] = 0;
}

__global__ void hist_kernel(const int* __restrict__ edge_dst) {
    int i = blockIdx.x * blockDim.x + threadIdx.x;
    if (i < N_EDGES) atomicAdd(&g_off[edge_dst[i] + 1], 1);
}

// single-block chunked inclusive scan of g_off[1..N]; also fills g_cur
__global__ void scan_kernel() {
    __shared__ int warp_sums[32];
    __shared__ int s_carry;
    const int t = threadIdx.x, lane = t & 31, w = t >> 5;
    if (t == 0) { s_carry = 0; g_cur[0] = 0; }
    __syncthreads();
    for (int base = 0; base < N_NODES; base += 1024) {
        int idx = base + t + 1;
        int v = (idx <= N_NODES) ? g_off[idx] : 0;
        int x = v;
        #pragma unroll
        for (int o = 1; o < 32; o <<= 1) {
            int y = __shfl_up_sync(0xffffffffu, x, o);
            if (lane >= o) x += y;
        }
        if (lane == 31) warp_sums[w] = x;
        __syncthreads();
        if (w == 0) {
            int s = warp_sums[lane];
            #pragma unroll
            for (int o = 1; o < 32; o <<= 1) {
                int y = __shfl_up_sync(0xffffffffu, s, o);
                if (lane >= o) s += y;
            }
            warp_sums[lane] = s;
        }
        __syncthreads();
        int pre  = (w > 0) ? warp_sums[w - 1] : 0;
        int incl = x + pre + s_carry;
        if (idx <= N_NODES) {
            g_off[idx] = incl;
            if (idx < N_NODES) g_cur[idx] = incl;
        }
        __syncthreads();
        if (t == 1023) s_carry = incl;
        __syncthreads();
    }
}

__global__ void scatter_kernel(const int* __restrict__ edge_src,
                               const int* __restrict__ edge_dst) {
    int i = blockIdx.x * blockDim.x + threadIdx.x;
    if (i >= N_EDGES) return;
    int s = edge_src[i];
    int d = edge_dst[i];
    float e = g_sl[s] + g_sr[d];
    e = (e > 0.f) ? e : NEG_SLOPE * e;
    int pos = atomicAdd(&g_cur[d], 1);
    g_ssrc[pos] = s;
    g_se[pos]   = e;
}

// ---------------- node phase: one warp per dst node, no output atomics ----------------
__global__ void node_kernel(float* __restrict__ out) {
    int gw   = (blockIdx.x * blockDim.x + threadIdx.x) >> 5;
    int lane = threadIdx.x & 31;
    if (gw >= N_NODES) return;
    int beg = g_off[gw];
    int end = g_off[gw + 1];

    float2 acc = make_float2(0.f, 0.f);
    if (beg < end) {
        // segment max
        float m = -__int_as_float(0x7f800000);   // -inf
        for (int j = beg + lane; j < end; j += 32) m = fmaxf(m, g_se[j]);
        #pragma unroll
        for (int o = 16; o; o >>= 1) m = fmaxf(m, __shfl_xor_sync(0xffffffffu, m, o));
        // denominator
        float den = 0.f;
        for (int j = beg + lane; j < end; j += 32) den += __expf(g_se[j] - m);
        #pragma unroll
        for (int o = 16; o; o >>= 1) den += __shfl_xor_sync(0xffffffffu, den, o);
        float invden = 1.0f / den;
        // weighted gather of z[src] rows (L2-resident)
        for (int j = beg; j < end; ++j) {
            int   s = g_ssrc[j];                         // broadcast load
            float a = __expf(g_se[j] - m) * invden;      // broadcast load + MUFU
            float2 zv = *(const float2*)&g_z[s * OUT_DIM + 2 * lane]; // coalesced 256B
            acc.x += a * zv.x;
            acc.y += a * zv.y;
        }
    }
    *(float2*)&out[gw * OUT_DIM + 2 * lane] = acc;
}

// ---------------- launch ----------------
extern "C" void kernel_launch(void* const* d_in, const int* in_sizes, int n_in,
                              void* d_out, int out_size) {
    const float* h        = (const float*)d_in[0];
    const int*   edge_src = (const int*)d_in[1];
    const int*   edge_dst = (const int*)d_in[2];
    const float* W_fc     = (const float*)d_in[3];
    const float* a_attn   = (const float*)d_in[4];
    float* out = (float*)d_out;

    const int SMEM = (IN_DIM * OUT_DIM) * 4 + (TILE_M / 2) * IN_DIM * 8; // 64KB + 128KB
    cudaFuncSetAttribute(gemm_kernel, cudaFuncAttributeMaxDynamicSharedMemorySize, SMEM);

    gemm_kernel<<<(N_NODES + TILE_M - 1) / TILE_M, 256, SMEM>>>(h, W_fc);
    s_kernel<<<(N_NODES * 32 + 255) / 256, 256>>>(a_attn);
    zero_kernel<<<(N_NODES + 256) / 256, 256>>>();
    hist_kernel<<<(N_EDGES + 255) / 256, 256>>>(edge_dst);
    scan_kernel<<<1, 1024>>>();
    scatter_kernel<<<(N_EDGES + 255) / 256, 256>>>(edge_src, edge_dst);
    node_kernel<<<(N_NODES * 32 + 255) / 256, 256>>>(out);
}